// round 3
// baseline (speedup 1.0000x reference)
#include <cuda_runtime.h>
#include <cuda_bf16.h>

#define N_NODES 50000
#define N_EDGES 800000
#define D 64

// ---------------------------------------------------------------------------
// Static device scratch (allocation-guard-legal)
// ---------------------------------------------------------------------------
__device__ int   g_cnt[N_NODES];
__device__ int   g_offs[N_NODES + 1];
__device__ int   g_cursor[N_NODES];
__device__ int   g_sorted[N_EDGES];
__device__ float g_neigh[N_NODES * D];

// ---------------------------------------------------------------------------
// 1) Histogram of destination degrees
// ---------------------------------------------------------------------------
__global__ __launch_bounds__(256) void hist_kernel(const int* __restrict__ dst,
                                                   int* __restrict__ cnt)
{
    int e = blockIdx.x * blockDim.x + threadIdx.x;
    if (e < N_EDGES) atomicAdd(&cnt[__ldg(dst + e)], 1);
}

// ---------------------------------------------------------------------------
// 2) Exclusive scan of 50k counters, single block of 1024 threads.
//    Also initializes the scatter cursors.
// ---------------------------------------------------------------------------
__global__ __launch_bounds__(1024) void scan_kernel(const int* __restrict__ cnt,
                                                    int* __restrict__ offs,
                                                    int* __restrict__ cursor)
{
    __shared__ int part[1024];
    const int PER = (N_NODES + 1023) / 1024;   // 49
    int t = threadIdx.x;
    int base = t * PER;

    int sum = 0;
    for (int i = 0; i < PER; i++) {
        int idx = base + i;
        if (idx < N_NODES) sum += __ldg(cnt + idx);
    }
    part[t] = sum;
    __syncthreads();

    // Kogge-Stone inclusive scan
    for (int off = 1; off < 1024; off <<= 1) {
        int v = (t >= off) ? part[t - off] : 0;
        __syncthreads();
        part[t] += v;
        __syncthreads();
    }
    int run = part[t] - sum;   // exclusive prefix for this thread's chunk

    for (int i = 0; i < PER; i++) {
        int idx = base + i;
        if (idx < N_NODES) {
            int c = __ldg(cnt + idx);
            offs[idx]   = run;
            cursor[idx] = run;
            run += c;
        }
    }
    if (t == 1023) offs[N_NODES] = run;  // total = N_EDGES
}

// ---------------------------------------------------------------------------
// 3) Scatter src indices into dst-sorted order
// ---------------------------------------------------------------------------
__global__ __launch_bounds__(256) void scatter_idx_kernel(
    const int* __restrict__ src, const int* __restrict__ dst,
    int* __restrict__ cursor, int* __restrict__ sorted)
{
    int e = blockIdx.x * blockDim.x + threadIdx.x;
    if (e >= N_EDGES) return;
    int d = __ldg(dst + e);
    int pos = atomicAdd(&cursor[d], 1);
    sorted[pos] = __ldg(src + e);
}

// ---------------------------------------------------------------------------
// 4) Per-node gather-sum: neigh[n] = sum_{e in CSR[n]} feat[sorted[e]]
//    16 lanes per node, one float4 per lane; edge loop unrolled x4 for MLP.
//    Single 16B write per lane — no RMW traffic.
// ---------------------------------------------------------------------------
__global__ __launch_bounds__(256) void gather_kernel(
    const float4* __restrict__ feat, const int* __restrict__ offs,
    const int* __restrict__ sorted, float4* __restrict__ neigh)
{
    int g = (blockIdx.x * blockDim.x + threadIdx.x) >> 4;   // node
    int c = threadIdx.x & 15;
    if (g >= N_NODES) return;

    int beg = __ldg(offs + g);
    int end = __ldg(offs + g + 1);

    float4 a = make_float4(0.f, 0.f, 0.f, 0.f);
    int e = beg;
    for (; e + 4 <= end; e += 4) {
        int s0 = __ldg(sorted + e);
        int s1 = __ldg(sorted + e + 1);
        int s2 = __ldg(sorted + e + 2);
        int s3 = __ldg(sorted + e + 3);
        float4 f0 = feat[s0 * 16 + c];
        float4 f1 = feat[s1 * 16 + c];
        float4 f2 = feat[s2 * 16 + c];
        float4 f3 = feat[s3 * 16 + c];
        a.x += (f0.x + f1.x) + (f2.x + f3.x);
        a.y += (f0.y + f1.y) + (f2.y + f3.y);
        a.z += (f0.z + f1.z) + (f2.z + f3.z);
        a.w += (f0.w + f1.w) + (f2.w + f3.w);
    }
    for (; e < end; e++) {
        int s = __ldg(sorted + e);
        float4 f = feat[s * 16 + c];
        a.x += f.x; a.y += f.y; a.z += f.z; a.w += f.w;
    }
    neigh[g * 16 + c] = a;
}

// ---------------------------------------------------------------------------
// 5) out = ((1+eps)*feat + neigh) @ W^T + b   using packed fma.rn.f32x2
//    Wt in smem transposed+interleaved so LDS.128 yields j-adjacent pairs.
// ---------------------------------------------------------------------------
#define GROWS 96

__global__ __launch_bounds__(GROWS) void gemm_kernel(
    const float4* __restrict__ feat, const float4* __restrict__ neigh,
    const float* __restrict__ W, const float* __restrict__ b,
    const float* __restrict__ eps, float4* __restrict__ out)
{
    __shared__ __align__(16) float Wt[64 * 64];    // Wt[k*64+j] = W[j][k], 16KB
    __shared__ float4 tile[GROWS * 17];            // padded row stride
    __shared__ __align__(8) float bsm[64];

    const int tid  = threadIdx.x;
    const int row0 = blockIdx.x * GROWS;

    for (int i = tid; i < 64 * 64; i += GROWS) {
        int j = i >> 6, k = i & 63;
        Wt[k * 64 + j] = W[i];
    }
    if (tid < 64) bsm[tid] = b[tid];
    float s = 1.0f + __ldg(eps);

    for (int i = tid; i < GROWS * 16; i += GROWS) {
        int r = i >> 4, c = i & 15;
        int gr = row0 + r;
        float4 v = make_float4(0.f, 0.f, 0.f, 0.f);
        if (gr < N_NODES) {
            float4 f = feat[gr * 16 + c];
            float4 n = neigh[gr * 16 + c];
            v.x = s * f.x + n.x;
            v.y = s * f.y + n.y;
            v.z = s * f.z + n.z;
            v.w = s * f.w + n.w;
        }
        tile[r * 17 + c] = v;
    }
    __syncthreads();

    // acc[2q] = {out[4q], out[4q+1]},  acc[2q+1] = {out[4q+2], out[4q+3]}
    unsigned long long acc[32];
#pragma unroll
    for (int p = 0; p < 32; p++) {
        float2 bb = ((const float2*)bsm)[p];
        asm("mov.b64 %0, {%1, %2};" : "=l"(acc[p]) : "f"(bb.x), "f"(bb.y));
    }

    for (int kq = 0; kq < 16; kq++) {
        float4 v = tile[tid * 17 + kq];
#pragma unroll
        for (int kk = 0; kk < 4; kk++) {
            float r = (kk == 0) ? v.x : (kk == 1) ? v.y : (kk == 2) ? v.z : v.w;
            unsigned long long rr;
            asm("mov.b64 %0, {%1, %1};" : "=l"(rr) : "f"(r));
            const ulonglong2* wrow =
                (const ulonglong2*)&Wt[(kq * 4 + kk) * 64];
#pragma unroll
            for (int q = 0; q < 16; q++) {
                ulonglong2 w = wrow[q];   // broadcast LDS.128 -> two b64 pairs
                asm("fma.rn.f32x2 %0, %1, %2, %0;"
                    : "+l"(acc[2 * q]) : "l"(rr), "l"(w.x));
                asm("fma.rn.f32x2 %0, %1, %2, %0;"
                    : "+l"(acc[2 * q + 1]) : "l"(rr), "l"(w.y));
            }
        }
    }

    // Restage through smem for coalesced stores
    __syncthreads();
#pragma unroll
    for (int q = 0; q < 16; q++) {
        float a0, a1, a2, a3;
        asm("mov.b64 {%0, %1}, %2;" : "=f"(a0), "=f"(a1) : "l"(acc[2 * q]));
        asm("mov.b64 {%0, %1}, %2;" : "=f"(a2), "=f"(a3) : "l"(acc[2 * q + 1]));
        tile[tid * 17 + q] = make_float4(a0, a1, a2, a3);
    }
    __syncthreads();

    for (int i = tid; i < GROWS * 16; i += GROWS) {
        int r = i >> 4, c = i & 15;
        int gr = row0 + r;
        if (gr < N_NODES) out[gr * 16 + c] = tile[r * 17 + c];
    }
}

// ---------------------------------------------------------------------------
// Launch: inputs per metadata order: feat, W, b, eps, src, dst
// ---------------------------------------------------------------------------
extern "C" void kernel_launch(void* const* d_in, const int* in_sizes, int n_in,
                              void* d_out, int out_size)
{
    const float4* feat = (const float4*)d_in[0];
    const float*  W    = (const float*)d_in[1];
    const float*  b    = (const float*)d_in[2];
    const float*  eps  = (const float*)d_in[3];
    const int*    src  = (const int*)d_in[4];
    const int*    dst  = (const int*)d_in[5];
    float4*       out  = (float4*)d_out;

    int *cnt, *offs, *cursor, *sorted;
    float* neigh;
    cudaGetSymbolAddress((void**)&cnt,    g_cnt);
    cudaGetSymbolAddress((void**)&offs,   g_offs);
    cudaGetSymbolAddress((void**)&cursor, g_cursor);
    cudaGetSymbolAddress((void**)&sorted, g_sorted);
    cudaGetSymbolAddress((void**)&neigh,  g_neigh);

    const int EB = (N_EDGES + 255) / 256;

    cudaMemsetAsync(cnt, 0, N_NODES * sizeof(int), 0);
    hist_kernel<<<EB, 256>>>(dst, cnt);
    scan_kernel<<<1, 1024>>>(cnt, offs, cursor);
    scatter_idx_kernel<<<EB, 256>>>(src, dst, cursor, sorted);
    {
        int threads = N_NODES * 16;
        gather_kernel<<<(threads + 255) / 256, 256>>>(feat, offs, sorted,
                                                      (float4*)neigh);
    }
    {
        int blocks = (N_NODES + GROWS - 1) / GROWS;
        gemm_kernel<<<blocks, GROWS>>>(feat, (const float4*)neigh, W, b, eps,
                                       out);
    }
}

// round 4
// speedup vs baseline: 2.1561x; 2.1561x over previous
#include <cuda_runtime.h>
#include <cuda_bf16.h>

#define N_NODES 50000
#define N_EDGES 800000
#define D 64
#define NBLK ((N_NODES + 255) / 256)   // 196

// ---------------------------------------------------------------------------
// Static device scratch (allocation-guard-legal)
// ---------------------------------------------------------------------------
__device__ int   g_cnt[N_NODES];
__device__ int   g_offs[N_NODES + 1];
__device__ int   g_cursor[N_NODES];
__device__ int   g_sorted[N_EDGES];
__device__ float g_neigh[N_NODES * D];
__device__ int   g_blkSum[NBLK];
__device__ int   g_blkBase[NBLK];

// ---------------------------------------------------------------------------
// 1) Histogram of destination degrees
// ---------------------------------------------------------------------------
__global__ __launch_bounds__(256) void hist_kernel(const int* __restrict__ dst,
                                                   int* __restrict__ cnt)
{
    int e = blockIdx.x * blockDim.x + threadIdx.x;
    if (e < N_EDGES) atomicAdd(&cnt[__ldg(dst + e)], 1);
}

// ---------------------------------------------------------------------------
// 2a) Per-block partial sums of the counters (196 blocks x 256)
// ---------------------------------------------------------------------------
__global__ __launch_bounds__(256) void partial_kernel(const int* __restrict__ cnt,
                                                      int* __restrict__ blkSum)
{
    __shared__ int sm[256];
    int idx = blockIdx.x * 256 + threadIdx.x;
    int v = (idx < N_NODES) ? __ldg(cnt + idx) : 0;
    sm[threadIdx.x] = v;
    __syncthreads();
    for (int off = 128; off > 0; off >>= 1) {
        if (threadIdx.x < off) sm[threadIdx.x] += sm[threadIdx.x + off];
        __syncthreads();
    }
    if (threadIdx.x == 0) blkSum[blockIdx.x] = sm[0];
}

// ---------------------------------------------------------------------------
// 2b) Exclusive scan of the 196 block sums (1 block x 256, Kogge-Stone)
// ---------------------------------------------------------------------------
__global__ __launch_bounds__(256) void scanbase_kernel(const int* __restrict__ blkSum,
                                                       int* __restrict__ blkBase)
{
    __shared__ int sm[256];
    int t = threadIdx.x;
    int v = (t < NBLK) ? __ldg(blkSum + t) : 0;
    sm[t] = v;
    __syncthreads();
    for (int off = 1; off < 256; off <<= 1) {
        int u = (t >= off) ? sm[t - off] : 0;
        __syncthreads();
        sm[t] += u;
        __syncthreads();
    }
    if (t < NBLK) blkBase[t] = sm[t] - v;   // exclusive
}

// ---------------------------------------------------------------------------
// 2c) Finalize offsets: per-block exclusive scan + block base
// ---------------------------------------------------------------------------
__global__ __launch_bounds__(256) void finalize_kernel(
    const int* __restrict__ cnt, const int* __restrict__ blkBase,
    int* __restrict__ offs, int* __restrict__ cursor)
{
    __shared__ int sm[256];
    int t = threadIdx.x;
    int idx = blockIdx.x * 256 + t;
    int c = (idx < N_NODES) ? __ldg(cnt + idx) : 0;
    sm[t] = c;
    __syncthreads();
    for (int off = 1; off < 256; off <<= 1) {
        int u = (t >= off) ? sm[t - off] : 0;
        __syncthreads();
        sm[t] += u;
        __syncthreads();
    }
    int off = __ldg(blkBase + blockIdx.x) + sm[t] - c;   // exclusive prefix
    if (idx < N_NODES) {
        offs[idx]   = off;
        cursor[idx] = off;
        if (idx == N_NODES - 1) offs[N_NODES] = off + c;  // = N_EDGES
    }
}

// ---------------------------------------------------------------------------
// 3) Scatter src indices into dst-sorted order
// ---------------------------------------------------------------------------
__global__ __launch_bounds__(256) void scatter_idx_kernel(
    const int* __restrict__ src, const int* __restrict__ dst,
    int* __restrict__ cursor, int* __restrict__ sorted)
{
    int e = blockIdx.x * blockDim.x + threadIdx.x;
    if (e >= N_EDGES) return;
    int d = __ldg(dst + e);
    int pos = atomicAdd(&cursor[d], 1);
    sorted[pos] = __ldg(src + e);
}

// ---------------------------------------------------------------------------
// 4) Per-node gather-sum (PROVEN: 18.1us). 16 lanes/node, float4 per lane.
// ---------------------------------------------------------------------------
__global__ __launch_bounds__(256) void gather_kernel(
    const float4* __restrict__ feat, const int* __restrict__ offs,
    const int* __restrict__ sorted, float4* __restrict__ neigh)
{
    int g = (blockIdx.x * blockDim.x + threadIdx.x) >> 4;   // node
    int c = threadIdx.x & 15;
    if (g >= N_NODES) return;

    int beg = __ldg(offs + g);
    int end = __ldg(offs + g + 1);

    float4 a = make_float4(0.f, 0.f, 0.f, 0.f);
    int e = beg;
    for (; e + 4 <= end; e += 4) {
        int s0 = __ldg(sorted + e);
        int s1 = __ldg(sorted + e + 1);
        int s2 = __ldg(sorted + e + 2);
        int s3 = __ldg(sorted + e + 3);
        float4 f0 = feat[s0 * 16 + c];
        float4 f1 = feat[s1 * 16 + c];
        float4 f2 = feat[s2 * 16 + c];
        float4 f3 = feat[s3 * 16 + c];
        a.x += (f0.x + f1.x) + (f2.x + f3.x);
        a.y += (f0.y + f1.y) + (f2.y + f3.y);
        a.z += (f0.z + f1.z) + (f2.z + f3.z);
        a.w += (f0.w + f1.w) + (f2.w + f3.w);
    }
    for (; e < end; e++) {
        int s = __ldg(sorted + e);
        float4 f = feat[s * 16 + c];
        a.x += f.x; a.y += f.y; a.z += f.z; a.w += f.w;
    }
    neigh[g * 16 + c] = a;
}

// ---------------------------------------------------------------------------
// 5) out = ((1+eps)*feat + neigh) @ W^T + b  (R2's PROVEN scalar-FFMA body,
//    with the eps-residual folded into the tile load)
// ---------------------------------------------------------------------------
#define GROWS 96

__global__ __launch_bounds__(GROWS) void gemm_kernel(
    const float4* __restrict__ feat, const float4* __restrict__ neigh,
    const float4* __restrict__ W, const float* __restrict__ b,
    const float* __restrict__ eps, float4* __restrict__ out)
{
    __shared__ float4 Wsm[64 * 16];       // Wsm[j*16 + kq] = W[j][4kq..4kq+3]
    __shared__ float4 tile[GROWS * 17];   // padded row stride: 17 float4
    __shared__ float  bsm[64];

    const int tid  = threadIdx.x;
    const int row0 = blockIdx.x * GROWS;

    for (int i = tid; i < 64 * 16; i += GROWS) Wsm[i] = W[i];
    if (tid < 64) bsm[tid] = b[tid];
    float s = 1.0f + __ldg(eps);

    for (int i = tid; i < GROWS * 16; i += GROWS) {
        int r = i >> 4, c = i & 15;
        int gr = row0 + r;
        float4 v = make_float4(0.f, 0.f, 0.f, 0.f);
        if (gr < N_NODES) {
            float4 f = feat[gr * 16 + c];
            float4 n = neigh[gr * 16 + c];
            v.x = s * f.x + n.x;
            v.y = s * f.y + n.y;
            v.z = s * f.z + n.z;
            v.w = s * f.w + n.w;
        }
        tile[r * 17 + c] = v;
    }
    __syncthreads();

    float acc[64];
#pragma unroll
    for (int j = 0; j < 64; j++) acc[j] = 0.f;

    for (int kq = 0; kq < 16; kq++) {           // NOT unrolled (I$)
        float4 v = tile[tid * 17 + kq];
#pragma unroll
        for (int j = 0; j < 64; j++) {          // broadcast LDS.128 of W
            float4 w = Wsm[j * 16 + kq];
            acc[j] += v.x * w.x + v.y * w.y + v.z * w.z + v.w * w.w;
        }
    }

#pragma unroll
    for (int j = 0; j < 64; j++) acc[j] += bsm[j];

    __syncthreads();
#pragma unroll
    for (int q = 0; q < 16; q++)
        tile[tid * 17 + q] =
            make_float4(acc[4 * q], acc[4 * q + 1], acc[4 * q + 2], acc[4 * q + 3]);
    __syncthreads();

    for (int i = tid; i < GROWS * 16; i += GROWS) {
        int r = i >> 4, c = i & 15;
        int gr = row0 + r;
        if (gr < N_NODES) out[gr * 16 + c] = tile[r * 17 + c];
    }
}

// ---------------------------------------------------------------------------
// Launch: inputs per metadata order: feat, W, b, eps, src, dst
// ---------------------------------------------------------------------------
extern "C" void kernel_launch(void* const* d_in, const int* in_sizes, int n_in,
                              void* d_out, int out_size)
{
    const float4* feat = (const float4*)d_in[0];
    const float4* W    = (const float4*)d_in[1];
    const float*  b    = (const float*)d_in[2];
    const float*  eps  = (const float*)d_in[3];
    const int*    src  = (const int*)d_in[4];
    const int*    dst  = (const int*)d_in[5];
    float4*       out  = (float4*)d_out;

    int *cnt, *offs, *cursor, *sorted, *blkSum, *blkBase;
    float* neigh;
    cudaGetSymbolAddress((void**)&cnt,     g_cnt);
    cudaGetSymbolAddress((void**)&offs,    g_offs);
    cudaGetSymbolAddress((void**)&cursor,  g_cursor);
    cudaGetSymbolAddress((void**)&sorted,  g_sorted);
    cudaGetSymbolAddress((void**)&neigh,   g_neigh);
    cudaGetSymbolAddress((void**)&blkSum,  g_blkSum);
    cudaGetSymbolAddress((void**)&blkBase, g_blkBase);

    const int EB = (N_EDGES + 255) / 256;

    cudaMemsetAsync(cnt, 0, N_NODES * sizeof(int), 0);
    hist_kernel<<<EB, 256>>>(dst, cnt);
    partial_kernel<<<NBLK, 256>>>(cnt, blkSum);
    scanbase_kernel<<<1, 256>>>(blkSum, blkBase);
    finalize_kernel<<<NBLK, 256>>>(cnt, blkBase, offs, cursor);
    scatter_idx_kernel<<<EB, 256>>>(src, dst, cursor, sorted);
    {
        int threads = N_NODES * 16;
        gather_kernel<<<(threads + 255) / 256, 256>>>(feat, offs, sorted,
                                                      (float4*)neigh);
    }
    {
        int blocks = (N_NODES + GROWS - 1) / GROWS;
        gemm_kernel<<<blocks, GROWS>>>(feat, (const float4*)neigh, W, b, eps,
                                       out);
    }
}